// round 15
// baseline (speedup 1.0000x reference)
#include <cuda_runtime.h>
#include <cstdint>

#define NT 1024
#define NW 32
#define TT 20
#define BIMG 64
#define GRID 256
#define NPART 192
#define AHALF 4704
#define CHALF 1568

__device__ float g_part[NPART * 3];
__device__ int g_done = 0;
__device__ unsigned long long g_best[BIMG][TT];   // zero-init; h0 resets each launch
__device__ int g_fA[BIMG], g_fB[BIMG], g_fC[BIMG];  // self-resetting flags
__device__ float g_halfF[BIMG][3];
__device__ int g_halfI[BIMG][2];
__device__ float g_nbce[BIMG][9408];

__device__ __forceinline__ float warpSumF(float v) {
    for (int o = 16; o > 0; o >>= 1) v += __shfl_down_sync(0xffffffffu, v, o);
    return v;
}
__device__ __forceinline__ int warpSumI(int v) {
    for (int o = 16; o > 0; o >>= 1) v += __shfl_down_sync(0xffffffffu, v, o);
    return v;
}

struct RedBuf {
    float f[NW + 1][3];
    int   i[NW + 1][2];
};

__device__ __forceinline__ void blockRed5(float& a, float& b, float& c,
                                          int& d, int& e, RedBuf* r) {
    int lane = threadIdx.x & 31, wid = threadIdx.x >> 5;
    a = warpSumF(a); b = warpSumF(b); c = warpSumF(c);
    d = warpSumI(d); e = warpSumI(e);
    if (lane == 0) {
        r->f[wid][0] = a; r->f[wid][1] = b; r->f[wid][2] = c;
        r->i[wid][0] = d; r->i[wid][1] = e;
    }
    __syncthreads();
    if (threadIdx.x < 32) {
        float aa = (lane < NW) ? r->f[lane][0] : 0.f;
        float bb = (lane < NW) ? r->f[lane][1] : 0.f;
        float cc = (lane < NW) ? r->f[lane][2] : 0.f;
        int   dd = (lane < NW) ? r->i[lane][0] : 0;
        int   ee = (lane < NW) ? r->i[lane][1] : 0;
        aa = warpSumF(aa); bb = warpSumF(bb); cc = warpSumF(cc);
        dd = warpSumI(dd); ee = warpSumI(ee);
        if (lane == 0) {
            r->f[NW][0] = aa; r->f[NW][1] = bb; r->f[NW][2] = cc;
            r->i[NW][0] = dd; r->i[NW][1] = ee;
        }
    }
    __syncthreads();
    a = r->f[NW][0]; b = r->f[NW][1]; c = r->f[NW][2];
    d = r->i[NW][0]; e = r->i[NW][1];
    __syncthreads();
}

// exact sum of the top-`need` values (3-level radix select over positive floats;
// zeros mark invalid). All NT threads participate; result broadcast to all.
__device__ float topk_sum(const uint4* __restrict__ src, int n4, int need,
                          int* hist, int* s_cnt, RedBuf* red) {
    const int tid = threadIdx.x;
    if (tid == 0) { s_cnt[0] = 0; s_cnt[1] = need; }
#pragma unroll
    for (int L = 0; L < 3; L++) {
        const int shift = (L == 0) ? 21 : (L == 1) ? 11 : 0;
        const int nb = (L == 2) ? 2048 : 1024;
        const int pshift = (L == 1) ? 21 : 11;
        for (int i = tid; i < nb; i += NT) hist[i] = 0;
        __syncthreads();
        unsigned u = (unsigned)s_cnt[0];
        unsigned upref = u >> pshift;
        for (int i = tid; i < n4; i += NT) {
            uint4 v = src[i];
            if (L == 0) {
                if (v.x) atomicAdd(&hist[v.x >> 21], 1);
                if (v.y) atomicAdd(&hist[v.y >> 21], 1);
                if (v.z) atomicAdd(&hist[v.z >> 21], 1);
                if (v.w) atomicAdd(&hist[v.w >> 21], 1);
            } else {
                if (v.x && (v.x >> pshift) == upref) atomicAdd(&hist[(v.x >> shift) & (nb - 1)], 1);
                if (v.y && (v.y >> pshift) == upref) atomicAdd(&hist[(v.y >> shift) & (nb - 1)], 1);
                if (v.z && (v.z >> pshift) == upref) atomicAdd(&hist[(v.z >> shift) & (nb - 1)], 1);
                if (v.w && (v.w >> pshift) == upref) atomicAdd(&hist[(v.w >> shift) & (nb - 1)], 1);
            }
        }
        __syncthreads();
        if (tid < 32) {
            const int bpl = nb / 32;
            int base = tid * bpl;
            int ls = 0;
            for (int j = 0; j < bpl; j++) ls += hist[base + j];
            int suf = ls;
#pragma unroll
            for (int o = 1; o < 32; o <<= 1) {
                int x = __shfl_down_sync(0xffffffffu, suf, o);
                if (tid + o < 32) suf += x;
            }
            int k = s_cnt[1];
            unsigned ball = __ballot_sync(0xffffffffu, suf >= k);
            int lsel = 31 - __clz(ball);
            if (tid == lsel) {
                int acc = suf - ls;
                for (int j = bpl - 1; j >= 0; j--) {
                    int hh = hist[base + j];
                    acc += hh;
                    if (acc >= k) {
                        s_cnt[1] = k - (acc - hh);
                        s_cnt[0] = (int)(((unsigned)s_cnt[0]) | ((unsigned)(base + j) << shift));
                        break;
                    }
                }
            }
        }
        __syncthreads();
    }
    unsigned u = (unsigned)s_cnt[0];
    float sgt = 0.f;
    int cgt = 0;
    for (int i = tid; i < n4; i += NT) {
        uint4 v = src[i];
        if (v.x > u) { sgt += __uint_as_float(v.x); cgt++; }
        if (v.y > u) { sgt += __uint_as_float(v.y); cgt++; }
        if (v.z > u) { sgt += __uint_as_float(v.z); cgt++; }
        if (v.w > u) { sgt += __uint_as_float(v.w); cgt++; }
    }
    int d1 = 0;
    float z1 = 0.f, z2 = 0.f;
    blockRed5(sgt, z1, z2, cgt, d1, red);
    return sgt + (float)(need - cgt) * __uint_as_float(u);
}

// write partials; last writer finalizes output
__device__ void tail_write(int slot, float obj_l, float cls_l, float loc_l,
                           RedBuf* red, float* out) {
    const int tid = threadIdx.x, lane = tid & 31;
    if (tid == 0) {
        g_part[slot * 3 + 0] = obj_l;
        g_part[slot * 3 + 1] = cls_l;
        g_part[slot * 3 + 2] = loc_l;
        __threadfence();
        int ticket = atomicAdd(&g_done, 1);
        red->i[0][0] = (ticket == NPART - 1) ? 1 : 0;
    }
    __syncthreads();
    if (red->i[0][0] && tid < 32) {
        __threadfence();
        float o = 0.f, c = 0.f, l = 0.f;
        for (int i = lane; i < NPART; i += 32) {
            o += g_part[i * 3 + 0];
            c += g_part[i * 3 + 1];
            l += g_part[i * 3 + 2];
        }
        o = warpSumF(o); c = warpSumF(c); l = warpSumF(l);
        if (lane == 0) {
            float ob = o / (float)BIMG;
            float cl = c / (float)BIMG;
            float lc = l / (float)BIMG;
            out[0] = ob; out[1] = cl; out[2] = lc;
            out[3] = ob + cl + 2.f * lc;
            g_done = 0;
        }
    }
}

// per-anchor phase-C core; _pc_cell = global cell index, _pc_lc = local cell
// index into s_val/s_mt. Internal names prefixed to avoid caller shadowing.
#define PHASE_C_BODY(F2_, cellexpr, lcexpr)                                     \
    {                                                                           \
        const int _pc_cell = (cellexpr);                                        \
        const int _pc_lc = (lcexpr);                                            \
        float _pc_obj0 = pb[4 * F2_ + _pc_cell];                                \
        float _pc_obj1 = pb[12 * F2_ + _pc_cell];                               \
        float _pc_obj2 = pb[20 * F2_ + _pc_cell];                               \
        int _pc_row = _pc_cell / F, _pc_col = _pc_cell - _pc_row * F;           \
        float _pc_cx = (_pc_col + 0.5f) * stride_f;                             \
        float _pc_cy = (_pc_row + 0.5f) * stride_f;                             \
        _Pragma("unroll")                                                       \
        for (int k = 0; k < 3; k++) {                                           \
            int a = _pc_lc * 3 + k;                                             \
            float iou = s_val[a];                                               \
            unsigned m = s_mt[a];                                               \
            bool ov = (m & 0x80) != 0;                                          \
            int t = m & 0x7F;                                                   \
            bool pos = ov || (iou >= 0.5f);                                     \
            bool neg = (!ov) && (iou < 0.3f);                                   \
            float x = (k == 0) ? _pc_obj0 : ((k == 1) ? _pc_obj1 : _pc_obj2);   \
            float sp = __logf(1.0f + __expf(-fabsf(x)));                        \
            float bce = fmaxf(x, 0.f) - (pos ? x : 0.f) + sp;                   \
            if (pos) {                                                          \
                np++; pbce += bce;                                              \
                int cb = k * 8;                                                 \
                float c0 = pb[(cb + 5) * F2_ + _pc_cell];                       \
                float c1 = pb[(cb + 6) * F2_ + _pc_cell];                       \
                float c2 = pb[(cb + 7) * F2_ + _pc_cell];                       \
                float mx = fmaxf(c0, fmaxf(c1, c2));                            \
                float lse = mx + __logf(__expf(c0 - mx) + __expf(c1 - mx) + __expf(c2 - mx)); \
                int tgt = s_tl[t] - 1;                                          \
                float ct = (tgt == 0) ? c0 : ((tgt == 1) ? c1 : c2);            \
                csum += lse - ct;                                               \
                float hk = (k == 0) ? h0s : ((k == 1) ? h1s : h2s);             \
                float aw = 2.f * hk;                                            \
                float4 tb = s_tb[t];                                            \
                float gw = tb.z - tb.x, gh = tb.w - tb.y;                       \
                float gcx = (tb.x + tb.z) * 0.5f, gcy = (tb.y + tb.w) * 0.5f;   \
                float td0 = (gcx - _pc_cx) / aw;                                \
                float td1 = (gcy - _pc_cy) / aw;                                \
                float td2 = __logf(gw / aw);                                    \
                float td3 = __logf(gh / aw);                                    \
                float d0 = pb[(cb + 0) * F2_ + _pc_cell];                       \
                float d1 = pb[(cb + 1) * F2_ + _pc_cell];                       \
                float d2 = pb[(cb + 2) * F2_ + _pc_cell];                       \
                float d3 = pb[(cb + 3) * F2_ + _pc_cell];                       \
                float e;                                                        \
                e = fabsf(d0 - td0); lsum += (e < 1.f) ? 0.5f * e * e : e - 0.5f; \
                e = fabsf(d1 - td1); lsum += (e < 1.f) ? 0.5f * e * e : e - 0.5f; \
                e = fabsf(d2 - td2); lsum += (e < 1.f) ? 0.5f * e * e : e - 0.5f; \
                e = fabsf(d3 - td3); lsum += (e < 1.f) ? 0.5f * e * e : e - 0.5f; \
            }                                                                   \
            s_val[a] = neg ? bce : 0.0f;                                        \
            nn += neg ? 1 : 0;                                                  \
        }                                                                       \
    }

// IoU inner core for one (cell,target); updates biou/bt/cand
#define IOU_CORE(cxv, cyv, cell_)                                               \
    _Pragma("unroll")                                                           \
    for (int k = 0; k < 3; k++) {                                               \
        float hk = (k == 0) ? h0s : ((k == 1) ? h1s : h2s);                     \
        float wx = fminf((cxv) + hk, tb.z) - fmaxf((cxv) - hk, tb.x);           \
        float wy = fminf((cyv) + hk, tb.w) - fmaxf((cyv) - hk, tb.y);           \
        wx = fmaxf(wx, 0.f); wy = fmaxf(wy, 0.f);                               \
        float inter = wx * wy;                                                  \
        float aarea = (2.f * hk) * (2.f * hk);                                  \
        float iou = inter / (aarea + ta - inter + 1e-9f);                       \
        if (iou > biou[k]) { biou[k] = iou; bt[k] = t; }                        \
        unsigned long long pk =                                                 \
            ((unsigned long long)__float_as_uint(iou) << 32) |                  \
            (unsigned long long)(0xFFFFFFFFu - (unsigned)((cell_) * 3 + k));    \
        if (pk > cand) cand = pk;                                               \
    }

// ---------------- single-block path (scales 1 and 2) ----------------
template <int F, int STRIDE>
__device__ void scale_single(
    int img, int slot, const float* __restrict__ pred,
    const float4* s_tb, const float* s_area, const int* s_tl,
    unsigned long long* s_best, unsigned* s_mask,
    float* s_val, unsigned char* s_mt, int* hist, RedBuf* red, int* s_cnt,
    float* out)
{
    constexpr int F2 = F * F;
    constexpr int A = F2 * 3;
    constexpr int TX = (F + 7) / 8;
    constexpr int TY = (F + 3) / 4;
    constexpr int NTILE = TX * TY;
    const float stride_f = (float)STRIDE;
    const float inv_s = 1.0f / stride_f;
    const float h0s = stride_f, h1s = 1.25f * stride_f, h2s = 1.5f * stride_f;
    const float* pb = pred + (size_t)img * 24 * F2;
    const int tid = threadIdx.x, lane = tid & 31, wid = tid >> 5;
    const int dx = lane & 7, dy = lane >> 3;

    if (tid < NTILE) s_mask[tid] = 0u;
    __syncthreads();
    if (tid < TT) {
        float4 tb = s_tb[tid];
        float lo_x = (tb.x - h2s) * inv_s, hi_x = (tb.z + h2s) * inv_s;
        float lo_y = (tb.y - h2s) * inv_s, hi_y = (tb.w + h2s) * inv_s;
        int tx0 = max(0, (int)floorf((lo_x - 7.5f) * 0.125f - 0.01f));
        int tx1 = min(TX - 1, (int)floorf((hi_x - 0.5f) * 0.125f + 0.01f));
        int ty0 = max(0, (int)floorf((lo_y - 3.5f) * 0.25f - 0.01f));
        int ty1 = min(TY - 1, (int)floorf((hi_y - 0.5f) * 0.25f + 0.01f));
        unsigned bit = 1u << tid;
        for (int r = ty0; r <= ty1; r++)
            for (int c = tx0; c <= tx1; c++)
                atomicOr(&s_mask[r * TX + c], bit);
    }
    __syncthreads();

    for (int ti = wid; ti < NTILE; ti += NW) {
        int tcol = ti % TX, trow = ti / TX;
        int col = tcol * 8 + dx, row = trow * 4 + dy;
        bool valid = (col < F) && (row < F);
        int cell = row * F + col;
        float cx = (col + 0.5f) * stride_f;
        float cy = (row + 0.5f) * stride_f;
        float biou[3] = {0.f, 0.f, 0.f};
        int bt[3] = {0, 0, 0};
        unsigned m = s_mask[ti];
        while (m) {
            int t = __ffs(m) - 1;
            m &= m - 1;
            float4 tb = s_tb[t];
            float ta = s_area[t];
            unsigned long long cand = 0ull;
            IOU_CORE(cx, cy, cell)
            if (valid && cand > 0xFFFFFFFFull) atomicMax(&s_best[t], cand);
        }
        if (valid) {
#pragma unroll
            for (int k = 0; k < 3; k++) {
                s_val[cell * 3 + k] = biou[k];
                s_mt[cell * 3 + k] = (unsigned char)bt[k];
            }
        }
    }
    __syncthreads();

    if (tid == 0) {
#pragma unroll
        for (int t = 0; t < TT; t++) {
            unsigned a = 0xFFFFFFFFu - (unsigned)(s_best[t] & 0xFFFFFFFFull);
            s_mt[a] = (unsigned char)(0x80 | t);
        }
    }
    __syncthreads();

    int np = 0, nn = 0;
    float pbce = 0.f, csum = 0.f, lsum = 0.f;
    for (int ci = tid; ci < F2; ci += NT)
        PHASE_C_BODY(F2, ci, ci)

    int tnp = np, tnn = nn;
    float tpb = pbce, tcs = csum, tls = lsum;
    blockRed5(tpb, tcs, tls, tnp, tnn, red);

    int need = min(3 * tnp, tnn);
    float topk = 0.f;
    if (need > 0)
        topk = topk_sum((const uint4*)s_val, A / 4, need, hist, s_cnt, red);

    tail_write(slot,
               (tpb + topk) / (float)max(tnp + need, 1),
               tcs / (float)max(tnp, 1),
               tls / (float)max(4 * tnp, 1), red, out);
}

// ---------------- split path (scale 0, two blocks per image) ----------------
__device__ void scale0_split(
    int img, int h, const float* __restrict__ pred,
    const float4* s_tb, const float* s_area, const int* s_tl,
    unsigned long long* s_best, unsigned* s_mask,
    float* s_val, unsigned char* s_mt, int* hist, RedBuf* red, int* s_cnt,
    float* out)
{
    constexpr int F = 56, F2 = 56 * 56;
    constexpr int TX = 7, NTILE_H = 49;
    const float stride_f = 8.f, inv_s = 0.125f;
    const float h0s = 8.f, h1s = 10.f, h2s = 12.f;
    const float* pb = pred + (size_t)img * 24 * F2;
    const int tid = threadIdx.x, lane = tid & 31, wid = tid >> 5;
    const int dx = lane & 7, dy = lane >> 3;
    const int trow_base = 7 * h;
    const int cell_base = CHALF * h;

    if (tid < NTILE_H) s_mask[tid] = 0u;
    __syncthreads();
    if (tid < TT) {
        float4 tb = s_tb[tid];
        float lo_x = (tb.x - h2s) * inv_s, hi_x = (tb.z + h2s) * inv_s;
        float lo_y = (tb.y - h2s) * inv_s, hi_y = (tb.w + h2s) * inv_s;
        int tx0 = max(0, (int)floorf((lo_x - 7.5f) * 0.125f - 0.01f));
        int tx1 = min(TX - 1, (int)floorf((hi_x - 0.5f) * 0.125f + 0.01f));
        int ty0 = max(trow_base, (int)floorf((lo_y - 3.5f) * 0.25f - 0.01f));
        int ty1 = min(trow_base + 6, (int)floorf((hi_y - 0.5f) * 0.25f + 0.01f));
        unsigned bit = 1u << tid;
        for (int r = ty0; r <= ty1; r++)
            for (int c = tx0; c <= tx1; c++)
                atomicOr(&s_mask[(r - trow_base) * TX + c], bit);
    }
    __syncthreads();

    // phase A over this half's 49 tiles (56x28 cells; no invalid lanes)
    for (int lt = wid; lt < NTILE_H; lt += NW) {
        int tcol = lt % TX, trow = trow_base + lt / TX;
        int col = tcol * 8 + dx, row = trow * 4 + dy;
        int cell = row * F + col;
        float cx = (col + 0.5f) * stride_f;
        float cy = (row + 0.5f) * stride_f;
        float biou[3] = {0.f, 0.f, 0.f};
        int bt[3] = {0, 0, 0};
        unsigned m = s_mask[lt];
        while (m) {
            int t = __ffs(m) - 1;
            m &= m - 1;
            float4 tb = s_tb[t];
            float ta = s_area[t];
            unsigned long long cand = 0ull;
            IOU_CORE(cx, cy, cell)
            if (cand > 0xFFFFFFFFull) atomicMax(&s_best[t], cand);
        }
        int la3 = (cell - cell_base) * 3;
#pragma unroll
        for (int k = 0; k < 3; k++) {
            s_val[la3 + k] = biou[k];
            s_mt[la3 + k] = (unsigned char)bt[k];
        }
    }
    __syncthreads();

    // merge local best keys into global, then 2-way flag barrier
    if (tid < TT) {
        atomicMax(&g_best[img][tid], s_best[tid]);
        __threadfence();
    }
    __syncthreads();
    if (tid == 0) {
        if (h == 0) {
            atomicExch(&g_fA[img], 1);
            while (atomicExch(&g_fB[img], 0) == 0) __nanosleep(32);
        } else {
            atomicExch(&g_fB[img], 1);
            while (atomicExch(&g_fA[img], 0) == 0) __nanosleep(32);
        }
        __threadfence();
    }
    __syncthreads();

    // phase B: apply overrides that land in this half (t ascending, last wins)
    if (tid == 0) {
#pragma unroll
        for (int t = 0; t < TT; t++) {
            unsigned long long bv = atomicAdd(&g_best[img][t], 0ull);
            unsigned a = 0xFFFFFFFFu - (unsigned)(bv & 0xFFFFFFFFull);
            int la = (int)a - AHALF * h;
            if (la >= 0 && la < AHALF) s_mt[la] = (unsigned char)(0x80 | t);
        }
    }
    __syncthreads();

    // phase C over this half's cells
    int np = 0, nn = 0;
    float pbce = 0.f, csum = 0.f, lsum = 0.f;
    for (int lci = tid; lci < CHALF; lci += NT)
        PHASE_C_BODY(F2, lci + cell_base, lci)

    int tnp = np, tnn = nn;
    float tpb = pbce, tcs = csum, tls = lsum;
    blockRed5(tpb, tcs, tls, tnp, tnn, red);

    // publish this half's neg-BCE to global scratch
    {
        uint4* dst = (uint4*)(&g_nbce[img][0]) + h * (AHALF / 4);
        const uint4* srcv = (const uint4*)s_val;
        for (int i = tid; i < AHALF / 4; i += NT) dst[i] = srcv[i];
    }
    __threadfence();
    __syncthreads();

    if (h == 1) {
        if (tid == 0) {
            g_halfF[img][0] = tpb; g_halfF[img][1] = tcs; g_halfF[img][2] = tls;
            g_halfI[img][0] = tnp; g_halfI[img][1] = tnn;
            __threadfence();
            atomicExch(&g_fC[img], 1);
        }
        return;
    }

    // h0: wait for h1, merge, select, finalize
    if (tid == 0) {
        while (atomicExch(&g_fC[img], 0) == 0) __nanosleep(32);
        __threadfence();
        red->f[0][0] = g_halfF[img][0];
        red->f[0][1] = g_halfF[img][1];
        red->f[0][2] = g_halfF[img][2];
        red->i[0][0] = g_halfI[img][0];
        red->i[0][1] = g_halfI[img][1];
    }
    __syncthreads();
    tpb += red->f[0][0]; tcs += red->f[0][1]; tls += red->f[0][2];
    tnp += red->i[0][0]; tnn += red->i[0][1];
    __syncthreads();
    if (tid < TT) g_best[img][tid] = 0ull;   // reset for next launch

    int need = min(3 * tnp, tnn);
    float topk = 0.f;
    if (need > 0)
        topk = topk_sum((const uint4*)(&g_nbce[img][0]), 9408 / 4, need,
                        hist, s_cnt, red);

    tail_write(img,
               (tpb + topk) / (float)max(tnp + need, 1),
               tcs / (float)max(tnp, 1),
               tls / (float)max(4 * tnp, 1), red, out);
}

__global__ void __launch_bounds__(NT) det_loss_kernel(
    const float* __restrict__ pred1, const float* __restrict__ pred2,
    const float* __restrict__ pred3,
    const float* __restrict__ tboxes, const int* __restrict__ tlabels,
    float* out)
{
    const int bid = blockIdx.x;
    int img;
    if (bid < 128) img = bid >> 1;
    else if (bid < 192) img = bid - 128;
    else img = bid - 192;

    __shared__ float4 s_tb[TT];
    __shared__ float s_area[TT];
    __shared__ int s_tl[TT];
    __shared__ unsigned long long s_best[TT];
    __shared__ RedBuf red;
    __shared__ int s_cnt[2];
    __shared__ unsigned s_mask[49];

    extern __shared__ unsigned char dynsm[];
    // layout: s_val[AN] floats, s_mt[AN] bytes, hist[2048] ints
    float* s_val = (float*)dynsm;

    if (threadIdx.x < TT) {
        int t = threadIdx.x;
        const float* tb = tboxes + ((size_t)img * TT + t) * 4;
        float x0 = tb[0], y0 = tb[1], x1 = tb[2], y1 = tb[3];
        s_tb[t] = make_float4(x0, y0, x1, y1);
        s_area[t] = (x1 - x0) * (y1 - y0);
        s_tl[t] = tlabels[img * TT + t];
        s_best[t] = (unsigned long long)0xFFFFFFFFu;  // guard: iou=0, anchor=0
    }
    __syncthreads();

    if (bid < 128) {
        unsigned char* s_mt = (unsigned char*)(s_val + AHALF);
        int* hist = (int*)(dynsm + AHALF * 5);
        scale0_split(img, bid & 1, pred1, s_tb, s_area, s_tl, s_best, s_mask,
                     s_val, s_mt, hist, &red, s_cnt, out);
    } else if (bid < 192) {
        unsigned char* s_mt = (unsigned char*)(s_val + 2352);
        int* hist = (int*)(dynsm + 2352 * 5);
        scale_single<28, 16>(img, 64 + img, pred2, s_tb, s_area, s_tl, s_best,
                             s_mask, s_val, s_mt, hist, &red, s_cnt, out);
    } else {
        unsigned char* s_mt = (unsigned char*)(s_val + 588);
        int* hist = (int*)(dynsm + 588 * 5);
        scale_single<14, 32>(img, 128 + img, pred3, s_tb, s_area, s_tl, s_best,
                             s_mask, s_val, s_mt, hist, &red, s_cnt, out);
    }
}

extern "C" void kernel_launch(void* const* d_in, const int* in_sizes, int n_in,
                              void* d_out, int out_size)
{
    const float* pred1  = (const float*)d_in[0];
    const float* pred2  = (const float*)d_in[1];
    const float* pred3  = (const float*)d_in[2];
    const float* tboxes = (const float*)d_in[6];
    const int*   tlab   = (const int*)d_in[7];
    float* out = (float*)d_out;

    const int smem = AHALF * 5 + 2048 * 4;  // 23520 + 8192 = 31712 B < 48KB
    det_loss_kernel<<<GRID, NT, smem>>>(pred1, pred2, pred3, tboxes, tlab, out);
}

// round 17
// speedup vs baseline: 1.1868x; 1.1868x over previous
#include <cuda_runtime.h>
#include <cstdint>

#define NT 1024
#define NW 32
#define TT 20
#define BIMG 64
#define NBLK 192
#define AMAX 9408

// per-block partial losses: [block][obj, cls, loc]
__device__ float g_part[NBLK * 3];
__device__ int g_done = 0;

__device__ __forceinline__ float warpSumF(float v) {
    for (int o = 16; o > 0; o >>= 1) v += __shfl_down_sync(0xffffffffu, v, o);
    return v;
}
__device__ __forceinline__ int warpSumI(int v) {
    for (int o = 16; o > 0; o >>= 1) v += __shfl_down_sync(0xffffffffu, v, o);
    return v;
}

struct RedBuf {
    float f[NW + 1][3];
    int   i[NW + 1][2];
};

// fused block reduction: 3 floats + 2 ints
__device__ __forceinline__ void blockRed5(float& a, float& b, float& c,
                                          int& d, int& e, RedBuf* r) {
    int lane = threadIdx.x & 31, wid = threadIdx.x >> 5;
    a = warpSumF(a); b = warpSumF(b); c = warpSumF(c);
    d = warpSumI(d); e = warpSumI(e);
    if (lane == 0) {
        r->f[wid][0] = a; r->f[wid][1] = b; r->f[wid][2] = c;
        r->i[wid][0] = d; r->i[wid][1] = e;
    }
    __syncthreads();
    if (threadIdx.x < 32) {
        float aa = (lane < NW) ? r->f[lane][0] : 0.f;
        float bb = (lane < NW) ? r->f[lane][1] : 0.f;
        float cc = (lane < NW) ? r->f[lane][2] : 0.f;
        int   dd = (lane < NW) ? r->i[lane][0] : 0;
        int   ee = (lane < NW) ? r->i[lane][1] : 0;
        aa = warpSumF(aa); bb = warpSumF(bb); cc = warpSumF(cc);
        dd = warpSumI(dd); ee = warpSumI(ee);
        if (lane == 0) {
            r->f[NW][0] = aa; r->f[NW][1] = bb; r->f[NW][2] = cc;
            r->i[NW][0] = dd; r->i[NW][1] = ee;
        }
    }
    __syncthreads();
    a = r->f[NW][0]; b = r->f[NW][1]; c = r->f[NW][2];
    d = r->i[NW][0]; e = r->i[NW][1];
    __syncthreads();
}

template <int F, int STRIDE>
__device__ __forceinline__ void scale_body(
    int img, int bid,
    const float* __restrict__ pred,
    const float4* s_tb, const float* s_area, const int* s_tl,
    unsigned long long* s_best, unsigned* s_mask,
    float* s_val, unsigned char* s_mt, RedBuf* red, int* s_cnt,
    float* out)
{
    constexpr int F2 = F * F;
    constexpr int A = F2 * 3;
    constexpr int TX = (F + 7) / 8;   // tiles in x (8 cols per tile)
    constexpr int TY = (F + 3) / 4;   // tiles in y (4 rows per tile)
    constexpr int NTILE = TX * TY;
    const float stride_f = (float)STRIDE;
    const float inv_s = 1.0f / stride_f;   // power of 2: exact
    const float h0 = stride_f, h1 = 1.25f * stride_f, h2 = 1.5f * stride_f;
    const float* pb = pred + (size_t)img * 24 * F2;
    const int tid = threadIdx.x, lane = tid & 31, wid = tid >> 5;
    const int dx = lane & 7, dy = lane >> 3;

    // ---- build per-tile target bitmask (tight, conservative-safe) ----
    if (tid < NTILE) s_mask[tid] = 0u;
    __syncthreads();
    if (tid < TT) {
        int t = tid;
        float4 tb = s_tb[t];
        float lo_x = (tb.x - h2) * inv_s, hi_x = (tb.z + h2) * inv_s;
        float lo_y = (tb.y - h2) * inv_s, hi_y = (tb.w + h2) * inv_s;
        int tx0 = max(0, (int)floorf((lo_x - 7.5f) * 0.125f - 0.01f));
        int tx1 = min(TX - 1, (int)floorf((hi_x - 0.5f) * 0.125f + 0.01f));
        int ty0 = max(0, (int)floorf((lo_y - 3.5f) * 0.25f - 0.01f));
        int ty1 = min(TY - 1, (int)floorf((hi_y - 0.5f) * 0.25f + 0.01f));
        unsigned bit = 1u << t;
        for (int r = ty0; r <= ty1; r++)
            for (int c = tx0; c <= tx1; c++)
                atomicOr(&s_mask[r * TX + c], bit);
    }
    __syncthreads();

    // ---- phase A: warp-tiled IoU over masked targets only ----
    for (int ti = wid; ti < NTILE; ti += NW) {
        int tcol = ti % TX, trow = ti / TX;
        int col = tcol * 8 + dx, row = trow * 4 + dy;
        bool valid = (col < F) && (row < F);
        int cell = row * F + col;
        float cx = (col + 0.5f) * stride_f;
        float cy = (row + 0.5f) * stride_f;

        float biou[3] = {0.f, 0.f, 0.f};
        int bt[3] = {0, 0, 0};
        unsigned m = s_mask[ti];
        while (m) {
            int t = __ffs(m) - 1;       // ascending t: ties -> lowest t (argmax)
            m &= m - 1;
            float4 tb = s_tb[t];
            float ta = s_area[t];
            unsigned long long cand = 0ull;
#pragma unroll
            for (int k = 0; k < 3; k++) {
                float hk = (k == 0) ? h0 : ((k == 1) ? h1 : h2);
                float wx = fminf(cx + hk, tb.z) - fmaxf(cx - hk, tb.x);
                float wy = fminf(cy + hk, tb.w) - fmaxf(cy - hk, tb.y);
                wx = fmaxf(wx, 0.f);
                wy = fmaxf(wy, 0.f);
                float inter = wx * wy;
                float aarea = (2.f * hk) * (2.f * hk);  // exact (ints in fp32)
                // exact division: decision-critical (pos/neg thresholds, argmax)
                float iou = inter / (aarea + ta - inter + 1e-9f);
                if (iou > biou[k]) { biou[k] = iou; bt[k] = t; }
                unsigned long long pk =
                    ((unsigned long long)__float_as_uint(iou) << 32) |
                    (unsigned long long)(0xFFFFFFFFu - (unsigned)(cell * 3 + k));
                if (pk > cand) cand = pk;
            }
            // only lanes with iou > 0 can beat the guard -> skip dead atomics
            if (valid && cand > 0xFFFFFFFFull) atomicMax(&s_best[t], cand);
        }
        if (valid) {
#pragma unroll
            for (int k = 0; k < 3; k++) {
                s_val[cell * 3 + k] = biou[k];
                s_mt[cell * 3 + k] = (unsigned char)bt[k];
            }
        }
    }
    __syncthreads();

    // ---- phase B: best-anchor override (sequential t: last-wins on dups) ----
    if (tid == 0) {
#pragma unroll
        for (int t = 0; t < TT; t++) {
            unsigned a = 0xFFFFFFFFu - (unsigned)(s_best[t] & 0xFFFFFFFFull);
            s_mt[a] = (unsigned char)(0x80 | t);
        }
    }
    __syncthreads();

    // ---- phase C: per-anchor losses (fast transcendentals: value-only paths) ----
    int np = 0, nn = 0;
    float pbce = 0.f, csum = 0.f, lsum = 0.f;
    for (int cell = tid; cell < F2; cell += NT) {
        float obj[3];
        obj[0] = pb[4 * F2 + cell];
        obj[1] = pb[12 * F2 + cell];
        obj[2] = pb[20 * F2 + cell];
        int row = cell / F, col = cell - row * F;
        float cx = (col + 0.5f) * stride_f;
        float cy = (row + 0.5f) * stride_f;
#pragma unroll
        for (int k = 0; k < 3; k++) {
            int a = cell * 3 + k;
            float iou = s_val[a];
            unsigned m = s_mt[a];
            bool ov = (m & 0x80) != 0;
            int t = m & 0x7F;
            bool pos = ov || (iou >= 0.5f);
            bool neg = (!ov) && (iou < 0.3f);
            float x = obj[k];
            // softplus(-|x|) via fast intrinsics (summed values only)
            float sp = __logf(1.0f + __expf(-fabsf(x)));
            float bce = fmaxf(x, 0.f) - (pos ? x : 0.f) + sp;

            if (pos) {
                np++;
                pbce += bce;
                int cb = k * 8;
                float c0 = pb[(cb + 5) * F2 + cell];
                float c1 = pb[(cb + 6) * F2 + cell];
                float c2 = pb[(cb + 7) * F2 + cell];
                float mx = fmaxf(c0, fmaxf(c1, c2));
                float lse = mx + __logf(__expf(c0 - mx) + __expf(c1 - mx) + __expf(c2 - mx));
                int tgt = s_tl[t] - 1;
                float ct = (tgt == 0) ? c0 : ((tgt == 1) ? c1 : c2);
                csum += lse - ct;

                float hk = (k == 0) ? h0 : ((k == 1) ? h1 : h2);
                float aw = 2.f * hk, ah = 2.f * hk;
                float4 tb = s_tb[t];
                float gw = tb.z - tb.x, gh = tb.w - tb.y;
                float gcx = (tb.x + tb.z) * 0.5f, gcy = (tb.y + tb.w) * 0.5f;
                float td0 = (gcx - cx) / aw;
                float td1 = (gcy - cy) / ah;
                float td2 = __logf(gw / aw);
                float td3 = __logf(gh / ah);
                float d0 = pb[(cb + 0) * F2 + cell];
                float d1 = pb[(cb + 1) * F2 + cell];
                float d2 = pb[(cb + 2) * F2 + cell];
                float d3 = pb[(cb + 3) * F2 + cell];
                float e;
                e = fabsf(d0 - td0); lsum += (e < 1.f) ? 0.5f * e * e : e - 0.5f;
                e = fabsf(d1 - td1); lsum += (e < 1.f) ? 0.5f * e * e : e - 0.5f;
                e = fabsf(d2 - td2); lsum += (e < 1.f) ? 0.5f * e * e : e - 0.5f;
                e = fabsf(d3 - td3); lsum += (e < 1.f) ? 0.5f * e * e : e - 0.5f;
            }
            // neg BCE (always > 0); invalid entries -> bit pattern 0
            s_val[a] = neg ? bce : 0.0f;
            nn += neg ? 1 : 0;
        }
    }

    int tnp = np, tnn = nn;
    float tpb = pbce, tcs = csum, tls = lsum;
    blockRed5(tpb, tcs, tls, tnp, tnn, red);

    // ---- phase D: exact top-`need` sum via 4-level radix-256 select ----
    // s_mt is dead after phase C -> reuse as 256-bin histogram
    int need = min(3 * tnp, tnn);
    float topk = 0.f;
    if (need > 0) {
        int* hist = (int*)s_mt;
        const uint4* v4 = (const uint4*)s_val;
        if (tid == 0) { s_cnt[0] = 0; s_cnt[1] = need; }
#pragma unroll
        for (int L = 0; L < 4; L++) {
            const int shift = (L == 0) ? 23 : (L == 1) ? 15 : (L == 2) ? 7 : 0;
            const int nb = (L == 3) ? 128 : 256;
            const int pshift = (L == 3) ? 7 : (shift + 8);
            if (tid < nb) hist[tid] = 0;
            __syncthreads();
            unsigned u = (unsigned)s_cnt[0];
            unsigned upref = u >> pshift;
            for (int i = tid; i < A / 4; i += NT) {
                uint4 v = v4[i];
                if (L == 0) {
                    if (v.x) atomicAdd(&hist[v.x >> 23], 1);
                    if (v.y) atomicAdd(&hist[v.y >> 23], 1);
                    if (v.z) atomicAdd(&hist[v.z >> 23], 1);
                    if (v.w) atomicAdd(&hist[v.w >> 23], 1);
                } else {
                    if (v.x && (v.x >> pshift) == upref) atomicAdd(&hist[(v.x >> shift) & (nb - 1)], 1);
                    if (v.y && (v.y >> pshift) == upref) atomicAdd(&hist[(v.y >> shift) & (nb - 1)], 1);
                    if (v.z && (v.z >> pshift) == upref) atomicAdd(&hist[(v.z >> shift) & (nb - 1)], 1);
                    if (v.w && (v.w >> pshift) == upref) atomicAdd(&hist[(v.w >> shift) & (nb - 1)], 1);
                }
            }
            __syncthreads();
            if (tid < 32) {
                const int bpl = nb / 32;      // bins per lane
                int base = tid * bpl;
                int ls = 0;
#pragma unroll
                for (int j = 0; j < 8; j++)
                    if (j < bpl) ls += hist[base + j];
                // suffix sum over lanes: suf(l) = sum of ls for lanes >= l
                int suf = ls;
#pragma unroll
                for (int o = 1; o < 32; o <<= 1) {
                    int x = __shfl_down_sync(0xffffffffu, suf, o);
                    if (tid + o < 32) suf += x;
                }
                int k = s_cnt[1];
                unsigned ball = __ballot_sync(0xffffffffu, suf >= k);
                int lsel = 31 - __clz(ball);  // largest lane with suf >= k
                if (tid == lsel) {
                    int acc = suf - ls;       // count in bins above this lane
                    for (int j = bpl - 1; j >= 0; j--) {
                        int h = hist[base + j];
                        acc += h;
                        if (acc >= k) {
                            s_cnt[1] = k - (acc - h);
                            s_cnt[0] = (int)(u | ((unsigned)(base + j) << shift));
                            break;
                        }
                    }
                }
            }
            __syncthreads();
        }
        unsigned u = (unsigned)s_cnt[0];
        // u = exact bits of the need-th largest; sum strictly greater + fill ties
        float sgt = 0.f;
        int cgt = 0;
        for (int i = tid; i < A / 4; i += NT) {
            uint4 v = v4[i];
            if (v.x > u) { sgt += __uint_as_float(v.x); cgt++; }
            if (v.y > u) { sgt += __uint_as_float(v.y); cgt++; }
            if (v.z > u) { sgt += __uint_as_float(v.z); cgt++; }
            if (v.w > u) { sgt += __uint_as_float(v.w); cgt++; }
        }
        int dummy1 = 0;
        float dz1 = 0.f, dz2 = 0.f;
        blockRed5(sgt, dz1, dz2, cgt, dummy1, red);
        topk = sgt + (float)(need - cgt) * __uint_as_float(u);
    }

    // ---- tail: write partials; last block finalizes ----
    if (tid == 0) {
        g_part[bid * 3 + 0] = (tpb + topk) / (float)max(tnp + need, 1);
        g_part[bid * 3 + 1] = tcs / (float)max(tnp, 1);
        g_part[bid * 3 + 2] = tls / (float)max(4 * tnp, 1);
        __threadfence();
        int ticket = atomicAdd(&g_done, 1);
        red->i[0][0] = (ticket == NBLK - 1) ? 1 : 0;
    }
    __syncthreads();
    if (red->i[0][0] && tid < 32) {
        __threadfence();
        float o = 0.f, c = 0.f, l = 0.f;
        for (int i = lane; i < NBLK; i += 32) {
            o += g_part[i * 3 + 0];
            c += g_part[i * 3 + 1];
            l += g_part[i * 3 + 2];
        }
        o = warpSumF(o); c = warpSumF(c); l = warpSumF(l);
        if (lane == 0) {
            float ob = o / (float)BIMG;
            float cl = c / (float)BIMG;
            float lc = l / (float)BIMG;
            out[0] = ob;
            out[1] = cl;
            out[2] = lc;
            out[3] = ob + cl + 2.f * lc;
            g_done = 0;  // reset for next graph replay
        }
    }
}

__global__ void __launch_bounds__(NT) det_loss_kernel(
    const float* __restrict__ pred1, const float* __restrict__ pred2,
    const float* __restrict__ pred3,
    const float* __restrict__ tboxes, const int* __restrict__ tlabels,
    float* out)
{
    const int bid = blockIdx.x;
    // heavy scale-0 blocks are bids 0..63 -> all land in wave 1 on distinct
    // SMs; wave 2 holds only tiny scale-2 blocks.
    const int scale = bid >> 6;
    const int img = bid & 63;

    __shared__ float4 s_tb[TT];
    __shared__ float s_area[TT];
    __shared__ int s_tl[TT];
    __shared__ unsigned long long s_best[TT];
    __shared__ RedBuf red;
    __shared__ int s_cnt[2];
    __shared__ unsigned s_mask[98];   // max tiles: F=56 -> 7x14

    extern __shared__ unsigned char dynsm[];
    float* s_val = (float*)dynsm;
    unsigned char* s_mt = (unsigned char*)(s_val + AMAX);

    if (threadIdx.x < TT) {
        int t = threadIdx.x;
        const float* tb = tboxes + ((size_t)img * TT + t) * 4;
        float x0 = tb[0], y0 = tb[1], x1 = tb[2], y1 = tb[3];
        s_tb[t] = make_float4(x0, y0, x1, y1);
        s_area[t] = (x1 - x0) * (y1 - y0);
        s_tl[t] = tlabels[img * TT + t];
        s_best[t] = (unsigned long long)0xFFFFFFFFu;  // guard: iou=0, anchor=0
    }
    __syncthreads();

    if (scale == 0)
        scale_body<56, 8>(img, bid, pred1, s_tb, s_area, s_tl, s_best, s_mask, s_val, s_mt, &red, s_cnt, out);
    else if (scale == 1)
        scale_body<28, 16>(img, bid, pred2, s_tb, s_area, s_tl, s_best, s_mask, s_val, s_mt, &red, s_cnt, out);
    else
        scale_body<14, 32>(img, bid, pred3, s_tb, s_area, s_tl, s_best, s_mask, s_val, s_mt, &red, s_cnt, out);
}

extern "C" void kernel_launch(void* const* d_in, const int* in_sizes, int n_in,
                              void* d_out, int out_size)
{
    const float* pred1  = (const float*)d_in[0];
    const float* pred2  = (const float*)d_in[1];
    const float* pred3  = (const float*)d_in[2];
    const float* tboxes = (const float*)d_in[6];
    const int*   tlab   = (const int*)d_in[7];
    float* out = (float*)d_out;

    const int smem = AMAX * 5;  // 47040 B dynamic + ~1.7KB static < 48KB
    det_loss_kernel<<<NBLK, NT, smem>>>(pred1, pred2, pred3, tboxes, tlab, out);
}